// round 6
// baseline (speedup 1.0000x reference)
#include <cuda_runtime.h>
#include <cuda_bf16.h>

#define BB      32
#define SS      64
#define DD      8
#define NEIDX   512
#define EMAX    150000
#define NW      8       // warps per CTA in fused kernel
#define NBC     128     // binning CTAs

// ---------------- device scratch ----------------
__device__ int g_part[NBC][NEIDX];
__device__ int g_base[NBC][NEIDX];
__device__ int g_bin_start[NEIDX + 1];
__device__ int g_sorted[EMAX];           // packed: c0 | (c1<<5)

// ---------------- K1: per-CTA histogram ----------------
__global__ __launch_bounds__(512) void k_hist(const int4* __restrict__ inc, int E) {
    __shared__ int sh[NEIDX];
    int tid = threadIdx.x;
    sh[tid] = 0;
    __syncthreads();
    int per = (E + NBC - 1) / NBC;
    int beg = blockIdx.x * per;
    int end = min(beg + per, E);
    for (int i = beg + tid; i < end; i += 512) {
        int4 r = inc[i];
        atomicAdd(&sh[r.z * DD + r.w], 1);
    }
    __syncthreads();
    g_part[blockIdx.x][tid] = sh[tid];
}

// ---------------- K2: scan ----------------
__global__ __launch_bounds__(NEIDX) void k_scan() {
    __shared__ int s[NEIDX];
    int t = threadIdx.x;
    int run = 0;
    #pragma unroll 8
    for (int c = 0; c < NBC; c++) {
        int v = g_part[c][t];
        g_base[c][t] = run;
        run += v;
    }
    s[t] = run;
    __syncthreads();
    for (int off = 1; off < NEIDX; off <<= 1) {
        int x = (t >= off) ? s[t - off] : 0;
        __syncthreads();
        s[t] += x;
        __syncthreads();
    }
    g_bin_start[t + 1] = s[t];
    if (t == 0) g_bin_start[0] = 0;
}

// ---------------- K3: scatter ----------------
__global__ __launch_bounds__(512) void k_scatter(const int4* __restrict__ inc, int E) {
    __shared__ int sc[NEIDX];
    int tid = threadIdx.x;
    sc[tid] = g_bin_start[tid] + g_base[blockIdx.x][tid];
    __syncthreads();
    int per = (E + NBC - 1) / NBC;
    int beg = blockIdx.x * per;
    int end = min(beg + per, E);
    for (int i = beg + tid; i < end; i += 512) {
        int4 r = inc[i];
        int b = r.z * DD + r.w;
        int pos = atomicAdd(&sc[b], 1);
        g_sorted[pos] = r.x | (r.y << 5);
    }
}

// ---------------- K4: fused edge MLP + segment mean + output MLP ----------------
// One CTA per eidx, 8 warps. In-CTA counting sort by c0, then warp-per-segment
// with lane = output channel: weights in registers, segment sum in a register.
__global__ __launch_bounds__(NW * 32) void k_fused(
    const float* __restrict__ nodes,
    const float* __restrict__ W0,  const float* __restrict__ b0,
    const float* __restrict__ W1,  const float* __restrict__ b1,
    const float* __restrict__ oW0, const float* __restrict__ ob0,
    const float* __restrict__ oW1, const float* __restrict__ ob1,
    float* __restrict__ out)
{
    __shared__ __align__(16) float s_h[NW][32];   // per-warp h staging (LDS.128 target)
    __shared__ __align__(16) float s_acc[BB * 32];
    __shared__ __align__(16) float s_ef[BB * 32];
    __shared__ __align__(16) float s_w0t[1024];   // out_core0 transposed [i][o]
    __shared__ __align__(16) float s_w1t[512];    // out_core1 transposed [i][o]
    __shared__ int   s_c1[640];          // c1 per c0-sorted edge
    __shared__ int   s_hist[32];
    __shared__ int   s_seg[33];
    __shared__ int   s_cur[32];
    __shared__ float s_ob0[32], s_ob1[16];

    int e    = blockIdx.x;
    int tid  = threadIdx.x;
    int warp = tid >> 5, lane = tid & 31;
    int c2   = e >> 3;

    // ---- load this lane's weight rows into registers (same for all warps) ----
    float w0r[16], w1r[32];
    {
        const float4* p0 = (const float4*)(W0 + e * 512 + lane * 16);
        #pragma unroll
        for (int q = 0; q < 4; q++) {
            float4 v = p0[q];
            w0r[q*4+0] = v.x; w0r[q*4+1] = v.y; w0r[q*4+2] = v.z; w0r[q*4+3] = v.w;
        }
        const float4* p1 = (const float4*)(W1 + e * 1024 + lane * 32);
        #pragma unroll
        for (int q = 0; q < 8; q++) {
            float4 v = p1[q];
            w1r[q*4+0] = v.x; w1r[q*4+1] = v.y; w1r[q*4+2] = v.z; w1r[q*4+3] = v.w;
        }
    }
    float rb0 = b0[e * 32 + lane];
    float rb1 = b1[e * 32 + lane];

    // ---- in-CTA counting sort of this bin by c0 ----
    int start = g_bin_start[e];
    int n     = g_bin_start[e + 1] - start;

    if (tid < 32) s_hist[tid] = 0;
    __syncthreads();
    for (int i = tid; i < n; i += NW * 32)
        atomicAdd(&s_hist[g_sorted[start + i] & 31], 1);
    __syncthreads();
    if (warp == 0) {
        int v = s_hist[lane];
        int x = v;
        #pragma unroll
        for (int off = 1; off < 32; off <<= 1) {
            int y = __shfl_up_sync(0xffffffffu, x, off);
            if (lane >= off) x += y;
        }
        s_seg[lane + 1] = x;
        s_cur[lane] = x - v;
        if (lane == 0) s_seg[0] = 0;
    }
    __syncthreads();
    for (int i = tid; i < n; i += NW * 32) {
        int p = g_sorted[start + i];
        int pos = atomicAdd(&s_cur[p & 31], 1);
        s_c1[pos] = p >> 5;
    }
    __syncthreads();

    // ---- per-segment compute: lane = o, register weights + register acc ----
    float* myh = s_h[warp];
    for (int c0 = warp; c0 < 32; c0 += NW) {
        int s = s_seg[c0], t = s_seg[c0 + 1];
        float acc = 0.f;
        for (int j = s; j < t; j++) {
            int c1 = s_c1[j];                       // LDS broadcast
            const float4* xp = (const float4*)(nodes + (c1 * SS + c2) * 16);
            float4 X0 = xp[0], X1 = xp[1], X2 = xp[2], X3 = xp[3]; // uniform LDG

            // layer 1 (4 partials)
            float h0 = rb0, h1 = 0.f, h2 = 0.f, h3 = 0.f;
            h0 = fmaf(w0r[0],  X0.x, h0); h1 = fmaf(w0r[1],  X0.y, h1);
            h2 = fmaf(w0r[2],  X0.z, h2); h3 = fmaf(w0r[3],  X0.w, h3);
            h0 = fmaf(w0r[4],  X1.x, h0); h1 = fmaf(w0r[5],  X1.y, h1);
            h2 = fmaf(w0r[6],  X1.z, h2); h3 = fmaf(w0r[7],  X1.w, h3);
            h0 = fmaf(w0r[8],  X2.x, h0); h1 = fmaf(w0r[9],  X2.y, h1);
            h2 = fmaf(w0r[10], X2.z, h2); h3 = fmaf(w0r[11], X2.w, h3);
            h0 = fmaf(w0r[12], X3.x, h0); h1 = fmaf(w0r[13], X3.y, h1);
            h2 = fmaf(w0r[14], X3.z, h2); h3 = fmaf(w0r[15], X3.w, h3);
            float h = fmaxf((h0 + h1) + (h2 + h3), 0.f);

            myh[lane] = h;
            __syncwarp();

            // layer 2: 8 LDS.128 broadcast + 32 FMA (4 partials)
            const float4* hp = (const float4*)myh;
            float g0 = rb1, g1 = 0.f, g2 = 0.f, g3 = 0.f;
            #pragma unroll
            for (int q = 0; q < 8; q += 4) {
                float4 H0 = hp[q+0], H1 = hp[q+1], H2 = hp[q+2], H3 = hp[q+3];
                g0 = fmaf(w1r[q*4+0],  H0.x, g0); g1 = fmaf(w1r[q*4+1],  H0.y, g1);
                g2 = fmaf(w1r[q*4+2],  H0.z, g2); g3 = fmaf(w1r[q*4+3],  H0.w, g3);
                g0 = fmaf(w1r[q*4+4],  H1.x, g0); g1 = fmaf(w1r[q*4+5],  H1.y, g1);
                g2 = fmaf(w1r[q*4+6],  H1.z, g2); g3 = fmaf(w1r[q*4+7],  H1.w, g3);
                g0 = fmaf(w1r[q*4+8],  H2.x, g0); g1 = fmaf(w1r[q*4+9],  H2.y, g1);
                g2 = fmaf(w1r[q*4+10], H2.z, g2); g3 = fmaf(w1r[q*4+11], H2.w, g3);
                g0 = fmaf(w1r[q*4+12], H3.x, g0); g1 = fmaf(w1r[q*4+13], H3.y, g1);
                g2 = fmaf(w1r[q*4+14], H3.z, g2); g3 = fmaf(w1r[q*4+15], H3.w, g3);
            }
            __syncwarp();
            acc += fmaxf((g0 + g1) + (g2 + g3), 0.f);
        }
        s_acc[c0 * 32 + lane] = acc;          // distinct c0 per warp: race-free
    }
    __syncthreads();

    // ---- stage output weights (transposed) + mean ----
    for (int t = tid; t < 1024; t += NW * 32) {
        int o = t >> 5, i = t & 31;
        s_w0t[i * 32 + o] = oW0[e * 1024 + t];
    }
    for (int t = tid; t < 512; t += NW * 32) {
        int o = t >> 5, i = t & 31;
        s_w1t[i * 16 + o] = oW1[e * 512 + t];
    }
    if (tid < 32) s_ob0[tid] = ob0[e * 32 + tid];
    if (tid < 16) s_ob1[tid] = ob1[e * 16 + tid];

    for (int t = tid; t < BB * 32; t += NW * 32) {
        int b_ = t >> 5;
        int c = s_hist[b_];
        s_ef[t] = (c > 0) ? s_acc[t] / (float)c : 0.f;
    }
    __syncthreads();

    // ---- out layer 1 (hh reuses s_acc) ----
    for (int t = tid; t < BB * 32; t += NW * 32) {
        int b_ = t >> 5, o = t & 31;
        float s = s_ob0[o];
        #pragma unroll
        for (int i = 0; i < 32; i++)
            s = fmaf(s_w0t[i * 32 + o], s_ef[b_ * 32 + i], s);
        s_acc[t] = fmaxf(s, 0.f);
    }
    __syncthreads();

    // ---- out layer 2 + store ----
    for (int t = tid; t < BB * 16; t += NW * 32) {
        int b_ = t >> 4, o = t & 15;
        float s = s_ob1[o];
        #pragma unroll
        for (int i = 0; i < 32; i++)
            s = fmaf(s_w1t[i * 16 + o], s_acc[b_ * 32 + i], s);
        out[(b_ * NEIDX + e) * 16 + o] = fmaxf(s, 0.f);
    }
}

// ---------------- launch ----------------
extern "C" void kernel_launch(void* const* d_in, const int* in_sizes, int n_in,
                              void* d_out, int out_size) {
    const float* nodes = (const float*)d_in[0];
    const float* ic0   = (const float*)d_in[1];
    const float* ib0   = (const float*)d_in[2];
    const float* ic1   = (const float*)d_in[3];
    const float* ib1   = (const float*)d_in[4];
    const float* oc0   = (const float*)d_in[5];
    const float* ob0   = (const float*)d_in[6];
    const float* oc1   = (const float*)d_in[7];
    const float* ob1   = (const float*)d_in[8];
    const int4*  inc   = (const int4*)d_in[9];
    int E = in_sizes[9] / 4;
    float* out = (float*)d_out;

    k_hist<<<NBC, 512>>>(inc, E);
    k_scan<<<1, NEIDX>>>();
    k_scatter<<<NBC, 512>>>(inc, E);
    k_fused<<<NEIDX, NW * 32>>>(nodes, ic0, ib0, ic1, ib1,
                                oc0, ob0, oc1, ob1, out);
}